// round 10
// baseline (speedup 1.0000x reference)
#include <cuda_runtime.h>

// Grid constants (match reference)
#define N_PIX_HI 512
#define NV_HI    256
#define N_PIX_LO 128
#define NV_LO    64
#define OUT_ELEMS (NV_LO * N_PIX_LO * N_PIX_LO)   // 1,048,576

#define INV_PIX_HI_F  40.0f     // 1/0.025 exactly
#define INV_DV_HI_F   0.32f     // 1/3.125 (~1ulp)
#define FOV_HALF_HI_F 6.3875f
#define VEL0_HI_F     -404.6875f

// Predicated scalar reduction (false predicate suppresses the access).
__device__ __forceinline__ void red_add(float* a, float v, int p) {
    asm volatile("{\n\t"
                 ".reg .pred q;\n\t"
                 "setp.ne.s32 q, %2, 0;\n\t"
                 "@q red.global.add.f32 [%0], %1;\n\t"
                 "}"
                 :: "l"(a), "f"(v), "r"(p) : "memory");
}

// Predicated vector reduction: one 16B-aligned sector RMW (sm_90+).
__device__ __forceinline__ void red_add_v4(float* a, float v0, float v1,
                                           float v2, float v3, int p) {
    asm volatile("{\n\t"
                 ".reg .pred q;\n\t"
                 "setp.ne.s32 q, %5, 0;\n\t"
                 "@q red.global.add.v4.f32 [%0], {%1, %2, %3, %4};\n\t"
                 "}"
                 :: "l"(a), "f"(v0), "f"(v1), "f"(v2), "f"(v3), "r"(p)
                 : "memory");
}

__device__ __forceinline__ void splat_point(float rr, float dd, float vv, float ff,
                                            float* __restrict__ out) {
    float x = (rr + FOV_HALF_HI_F) * INV_PIX_HI_F;
    float y = (dd + FOV_HALF_HI_F) * INV_PIX_HI_F;
    float v = (vv - VEL0_HI_F)     * INV_DV_HI_F;

    float xf = floorf(x), yf = floorf(y), vf = floorf(v);
    int ix0 = (int)xf, iy0 = (int)yf, iv0 = (int)vf;
    float fx = x - xf, fy = y - yf, fv = v - vf;

    int valid = ((unsigned)ix0 < N_PIX_HI - 1) &
                ((unsigned)iy0 < N_PIX_HI - 1) &
                ((unsigned)iv0 < NV_HI - 1);

    // split flags: hi-res corner i0+1 lands in a different low-res cell
    int sx = (ix0 & 3) == 3;
    int sy = (iy0 & 3) == 3;
    int sv = (iv0 & 3) == 3;

    // merged y/v lo-corner weights (fold hi-corner to 1.0 when not split)
    float wy0 = sy ? (1.0f - fy) : 1.0f;
    float wv0 = sv ? (1.0f - fv) : 1.0f;

    float f = ff * (1.0f / 64.0f);   // block-mean folded in

    int cx0 = ix0 >> 2, cy0 = iy0 >> 2, cv0 = iv0 >> 2;

    // x pattern inside the aligned 4-cell quad; untouched slots add 0.0f.
    int q = cx0 & 3;
    float t0 = sx ? (1.0f - fx) : 1.0f;   // lo-corner weight (merged)
    float t1 = sx ? fx : 0.0f;            // hi-corner weight (0 when merged)
    float u0 = (q == 0) ? t0 : 0.0f;
    float u1 = (q == 1) ? t0 : ((q == 0) ? t1 : 0.0f);
    float u2 = (q == 2) ? t0 : ((q == 1) ? t1 : 0.0f);
    float u3 = (q == 3) ? t0 : ((q == 2) ? t1 : 0.0f);
    int straddle = (q == 3) & sx;         // hi-corner spills into next quad

    // 16B-aligned quad base (row stride 128 floats -> quad never crosses row)
    float* oq = out + ((cv0 * N_PIX_LO + cy0) * N_PIX_LO + (cx0 & ~3));

    float a0 = f * wv0 * wy0;   // (v0,y0)
    float a1 = f * wv0 * fy;    // (v0,y1) - only if sy
    float a2 = f * fv  * wy0;   // (v1,y0) - only if sv
    float a3 = f * fv  * fy;    // (v1,y1) - only if sv&sy

    const int SY = N_PIX_LO;
    const int SV = N_PIX_LO * N_PIX_LO;

    red_add_v4(oq,           a0*u0, a0*u1, a0*u2, a0*u3, valid);
    red_add_v4(oq + SY,      a1*u0, a1*u1, a1*u2, a1*u3, valid & sy);
    red_add_v4(oq + SV,      a2*u0, a2*u1, a2*u2, a2*u3, valid & sv);
    red_add_v4(oq + SV + SY, a3*u0, a3*u1, a3*u2, a3*u3, valid & sv & sy);

    // straddle spill: hi x-corner in the next quad's slot 0 (rare, P=1/16)
    red_add(oq + 4,           a0 * t1, valid & straddle);
    red_add(oq + 4 + SY,      a1 * t1, valid & straddle & sy);
    red_add(oq + 4 + SV,      a2 * t1, valid & straddle & sv);
    red_add(oq + 4 + SV + SY, a3 * t1, valid & straddle & sv & sy);
}

__global__ void __launch_bounds__(256) splat_kernel(
        const float* __restrict__ ra,
        const float* __restrict__ dec,
        const float* __restrict__ vel,
        const float* __restrict__ flux,
        float* __restrict__ out,
        int n) {
    int t = blockIdx.x * blockDim.x + threadIdx.x;
    int base = t * 2;
    if (base + 1 < n) {
        // Both points' data loaded up-front (REDs' memory clobber would
        // otherwise forbid hoisting the second point's loads).
        float2 r2 = *(const float2*)(ra   + base);
        float2 d2 = *(const float2*)(dec  + base);
        float2 v2 = *(const float2*)(vel  + base);
        float2 f2 = *(const float2*)(flux + base);
        splat_point(r2.x, d2.x, v2.x, f2.x, out);
        splat_point(r2.y, d2.y, v2.y, f2.y, out);
    } else if (base < n) {
        splat_point(ra[base], dec[base], vel[base], flux[base], out);
    }
}

extern "C" void kernel_launch(void* const* d_in, const int* in_sizes, int n_in,
                              void* d_out, int out_size) {
    const float* ra   = (const float*)d_in[0];
    const float* dec  = (const float*)d_in[1];
    const float* vel  = (const float*)d_in[2];
    const float* flux = (const float*)d_in[3];
    float* out = (float*)d_out;
    int n = in_sizes[0];

    cudaMemsetAsync(out, 0, OUT_ELEMS * sizeof(float));

    int nt = (n + 1) / 2;
    splat_kernel<<<(nt + 255) / 256, 256>>>(ra, dec, vel, flux, out, n);
}

// round 11
// speedup vs baseline: 1.0228x; 1.0228x over previous
#include <cuda_runtime.h>

// Grid constants (match reference)
#define N_PIX_HI 512
#define NV_HI    256
#define N_PIX_LO 128
#define NV_LO    64
#define OUT_ELEMS (NV_LO * N_PIX_LO * N_PIX_LO)   // 1,048,576

#define INV_PIX_HI_F  40.0f     // 1/0.025 exactly
#define INV_DV_HI_F   0.32f     // 1/3.125 (~1ulp)
#define FOV_HALF_HI_F 6.3875f
#define VEL0_HI_F     -404.6875f

// Byte offsets inside the output cube (row = 128 floats, plane = 16384 floats)
// +SY = 512 B, +SV = 65536 B, +SV+SY = 66048 B, straddle +16 B variants.

__global__ void __launch_bounds__(256) splat_kernel(
        const float* __restrict__ ra,
        const float* __restrict__ dec,
        const float* __restrict__ vel,
        const float* __restrict__ flux,
        float* __restrict__ out,
        int n) {
    int i = blockIdx.x * blockDim.x + threadIdx.x;
    if (i >= n) return;

    float x = (ra[i]  + FOV_HALF_HI_F) * INV_PIX_HI_F;
    float y = (dec[i] + FOV_HALF_HI_F) * INV_PIX_HI_F;
    float v = (vel[i] - VEL0_HI_F)     * INV_DV_HI_F;

    float xf = floorf(x), yf = floorf(y), vf = floorf(v);
    int ix0 = (int)xf, iy0 = (int)yf, iv0 = (int)vf;
    float fx = x - xf, fy = y - yf, fv = v - vf;

    int valid = ((unsigned)ix0 < N_PIX_HI - 1) &
                ((unsigned)iy0 < N_PIX_HI - 1) &
                ((unsigned)iv0 < NV_HI - 1);

    // split flags: hi-res corner i0+1 lands in a different low-res cell
    int sx = (ix0 & 3) == 3;
    int sy = (iy0 & 3) == 3;
    int sv = (iv0 & 3) == 3;

    // merged y/v lo-corner weights (hi-corner folds to 1.0 when not split)
    float wy0 = sy ? (1.0f - fy) : 1.0f;
    float wv0 = sv ? (1.0f - fv) : 1.0f;

    float f = flux[i] * (1.0f / 64.0f);   // block-mean folded in

    int cx0 = ix0 >> 2, cy0 = iy0 >> 2, cv0 = iv0 >> 2;

    // x placement inside the aligned 4-cell quad; untouched slots add 0.0f.
    int q = cx0 & 3;
    float t0 = sx ? (1.0f - fx) : 1.0f;   // lo-corner weight (merged)
    float t1 = sx ? fx : 0.0f;            // hi-corner weight (0 when merged)
    float u0 = (q == 0) ? t0 : 0.0f;
    float u1 = (q == 1) ? t0 : ((q == 0) ? t1 : 0.0f);
    float u2 = (q == 2) ? t0 : ((q == 1) ? t1 : 0.0f);
    float u3 = (q == 3) ? t0 : ((q == 2) ? t1 : 0.0f);
    int st = (q == 3) & sx;               // hi-corner spills into next quad

    // 16B-aligned quad base (row stride 128 floats -> quad never crosses row)
    float* oq = out + ((cv0 * N_PIX_LO + cy0) * N_PIX_LO + (cx0 & ~3));

    float a0 = f * wv0 * wy0;   // (v0,y0)
    float a1 = f * wv0 * fy;    // (v0,y1) - only if sy
    float a2 = f * fv  * wy0;   // (v1,y0) - only if sv
    float a3 = f * fv  * fy;    // (v1,y1) - only if sv&sy

    // All 8 predicated reductions in ONE asm block:
    //  - 8 pred-ops via setp.and chains (replaces per-call setp + LOP3s)
    //  - immediate byte offsets (replaces per-call 64-bit address math)
    //  - single memory clobber (lets ptxas schedule everything above freely)
    // False predicates suppress the access entirely.
    asm volatile(
        "{\n\t"
        ".reg .pred pv, py, pz, pzy, ps, psy, psz, pszy;\n\t"
        "setp.ne.s32      pv,   %21, 0;\n\t"            // valid
        "setp.ne.and.s32  py,   %22, 0, pv;\n\t"        // valid & sy
        "setp.ne.and.s32  pz,   %23, 0, pv;\n\t"        // valid & sv
        "setp.ne.and.s32  pzy,  %22, 0, pz;\n\t"        // valid & sv & sy
        "setp.ne.and.s32  ps,   %24, 0, pv;\n\t"        // valid & straddle
        "setp.ne.and.s32  psy,  %22, 0, ps;\n\t"        // .. & sy
        "setp.ne.and.s32  psz,  %23, 0, ps;\n\t"        // .. & sv
        "setp.ne.and.s32  pszy, %22, 0, psz;\n\t"       // .. & sv & sy
        "@pv   red.global.add.v4.f32 [%0],       {%1, %2, %3, %4};\n\t"
        "@py   red.global.add.v4.f32 [%0+512],   {%5, %6, %7, %8};\n\t"
        "@pz   red.global.add.v4.f32 [%0+65536], {%9, %10, %11, %12};\n\t"
        "@pzy  red.global.add.v4.f32 [%0+66048], {%13, %14, %15, %16};\n\t"
        "@ps   red.global.add.f32    [%0+16],    %17;\n\t"
        "@psy  red.global.add.f32    [%0+528],   %18;\n\t"
        "@psz  red.global.add.f32    [%0+65552], %19;\n\t"
        "@pszy red.global.add.f32    [%0+66064], %20;\n\t"
        "}"
        :: "l"(oq),
           "f"(a0*u0), "f"(a0*u1), "f"(a0*u2), "f"(a0*u3),
           "f"(a1*u0), "f"(a1*u1), "f"(a1*u2), "f"(a1*u3),
           "f"(a2*u0), "f"(a2*u1), "f"(a2*u2), "f"(a2*u3),
           "f"(a3*u0), "f"(a3*u1), "f"(a3*u2), "f"(a3*u3),
           "f"(a0*t1), "f"(a1*t1), "f"(a2*t1), "f"(a3*t1),
           "r"(valid), "r"(sy), "r"(sv), "r"(st)
        : "memory");
}

extern "C" void kernel_launch(void* const* d_in, const int* in_sizes, int n_in,
                              void* d_out, int out_size) {
    const float* ra   = (const float*)d_in[0];
    const float* dec  = (const float*)d_in[1];
    const float* vel  = (const float*)d_in[2];
    const float* flux = (const float*)d_in[3];
    float* out = (float*)d_out;
    int n = in_sizes[0];

    cudaMemsetAsync(out, 0, OUT_ELEMS * sizeof(float));

    splat_kernel<<<(n + 255) / 256, 256>>>(ra, dec, vel, flux, out, n);
}

// round 15
// speedup vs baseline: 1.0322x; 1.0092x over previous
#include <cuda_runtime.h>

// Grid constants (match reference)
#define N_PIX_HI 512
#define NV_HI    256
#define N_PIX_LO 128
#define NV_LO    64
#define OUT_ELEMS (NV_LO * N_PIX_LO * N_PIX_LO)   // 1,048,576

#define INV_PIX_HI_F  40.0f     // 1/0.025 exactly
#define INV_DV_HI_F   0.32f     // 1/3.125 (~1ulp)
#define FOV_HALF_HI_F 6.3875f
#define VEL0_HI_F     -404.6875f

// Byte offsets in the cube: +y row = 512 B, +v plane = 65536 B.

__global__ void __launch_bounds__(256) splat_kernel(
        const float* __restrict__ ra,
        const float* __restrict__ dec,
        const float* __restrict__ vel,
        const float* __restrict__ flux,
        float* __restrict__ out,
        int n) {
    int i = blockIdx.x * blockDim.x + threadIdx.x;
    if (i >= n) return;

    float x = (ra[i]  + FOV_HALF_HI_F) * INV_PIX_HI_F;
    float y = (dec[i] + FOV_HALF_HI_F) * INV_PIX_HI_F;
    float v = (vel[i] - VEL0_HI_F)     * INV_DV_HI_F;

    float xf = floorf(x), yf = floorf(y), vf = floorf(v);
    int ix0 = (int)xf, iy0 = (int)yf, iv0 = (int)vf;
    float fx = x - xf, fy = y - yf, fv = v - vf;

    int valid = ((unsigned)ix0 < N_PIX_HI - 1) &
                ((unsigned)iy0 < N_PIX_HI - 1) &
                ((unsigned)iv0 < NV_HI - 1);

    // split flags: hi-res corner i0+1 lands in a different low-res cell
    int sx = (ix0 & 3) == 3;
    int sy = (iy0 & 3) == 3;
    int sv = (iv0 & 3) == 3;

    // merged y/v lo-corner weights (hi-corner folds to 1.0 when not split)
    float wy0 = sy ? (1.0f - fy) : 1.0f;
    float wv0 = sv ? (1.0f - fv) : 1.0f;

    float f = flux[i] * (1.0f / 64.0f);   // block-mean folded in

    int cx0 = ix0 >> 2, cy0 = iy0 >> 2, cv0 = iv0 >> 2;

    // x placement inside the 8B-aligned 2-cell pair; untouched slot adds 0.0f.
    float t0 = sx ? (1.0f - fx) : 1.0f;   // lo-corner weight (merged)
    float t1 = sx ? fx : 0.0f;            // hi-corner weight (0 when merged)
    int odd = cx0 & 1;
    float e0 = odd ? 0.0f : t0;
    float e1 = odd ? t0 : t1;
    int st = odd & sx;                    // hi-corner spills into next pair

    // 8B-aligned pair base (row stride 128 floats -> pair never crosses row)
    float* op = out + ((cv0 * N_PIX_LO + cy0) * N_PIX_LO + (cx0 & ~1));

    float a0 = f * wv0 * wy0;   // (v0,y0)
    float a1 = f * wv0 * fy;    // (v0,y1) - only if sy
    float a2 = f * fv  * wy0;   // (v1,y0) - only if sv
    float a3 = f * fv  * fy;    // (v1,y1) - only if sv&sy

    // 4 v2 REDs (x-pair per (y,v) corner) + 4 rare straddle scalars,
    // one asm block, immediate offsets, single memory clobber.
    asm volatile(
        "{\n\t"
        ".reg .pred pv, py, pz, pzy, ps, psy, psz, pszy;\n\t"
        "setp.ne.s32      pv,   %13, 0;\n\t"            // valid
        "setp.ne.and.s32  py,   %14, 0, pv;\n\t"        // valid & sy
        "setp.ne.and.s32  pz,   %15, 0, pv;\n\t"        // valid & sv
        "setp.ne.and.s32  pzy,  %14, 0, pz;\n\t"        // valid & sv & sy
        "setp.ne.and.s32  ps,   %16, 0, pv;\n\t"        // valid & straddle
        "setp.ne.and.s32  psy,  %14, 0, ps;\n\t"        // .. & sy
        "setp.ne.and.s32  psz,  %15, 0, ps;\n\t"        // .. & sv
        "setp.ne.and.s32  pszy, %14, 0, psz;\n\t"       // .. & sv & sy
        "@pv   red.global.add.v2.f32 [%0],       {%1, %2};\n\t"
        "@py   red.global.add.v2.f32 [%0+512],   {%3, %4};\n\t"
        "@pz   red.global.add.v2.f32 [%0+65536], {%5, %6};\n\t"
        "@pzy  red.global.add.v2.f32 [%0+66048], {%7, %8};\n\t"
        "@ps   red.global.add.f32    [%0+8],     %9;\n\t"
        "@psy  red.global.add.f32    [%0+520],   %10;\n\t"
        "@psz  red.global.add.f32    [%0+65544], %11;\n\t"
        "@pszy red.global.add.f32    [%0+66056], %12;\n\t"
        "}"
        :: "l"(op),
           "f"(a0*e0), "f"(a0*e1),
           "f"(a1*e0), "f"(a1*e1),
           "f"(a2*e0), "f"(a2*e1),
           "f"(a3*e0), "f"(a3*e1),
           "f"(a0*t1), "f"(a1*t1), "f"(a2*t1), "f"(a3*t1),
           "r"(valid), "r"(sy), "r"(sv), "r"(st)
        : "memory");
}

extern "C" void kernel_launch(void* const* d_in, const int* in_sizes, int n_in,
                              void* d_out, int out_size) {
    const float* ra   = (const float*)d_in[0];
    const float* dec  = (const float*)d_in[1];
    const float* vel  = (const float*)d_in[2];
    const float* flux = (const float*)d_in[3];
    float* out = (float*)d_out;
    int n = in_sizes[0];

    cudaMemsetAsync(out, 0, OUT_ELEMS * sizeof(float));

    splat_kernel<<<(n + 255) / 256, 256>>>(ra, dec, vel, flux, out, n);
}